// round 8
// baseline (speedup 1.0000x reference)
#include <cuda_runtime.h>
#include <cuda_fp16.h>
#include <cstdint>

#define B_ 8
#define C_ 256
#define N_ 4096
#define K_ 64
#define MT 32
#define NB 64                            // q-rows per CTA (4 warps)
#define LOG2E 1.4426950408889634f

// Scratch (fp16 hi/lo packed). F/G rows: 64 u32 = [hi-pair0, lo-pair0, hi-pair1, ...]
// pair p = (k=2p, k=2p+1). H: fp16 single, TRANSPOSED [b][d][n].
__device__ uint32_t g_F[(size_t)B_ * N_ * 64];
__device__ uint32_t g_G[(size_t)B_ * N_ * 64];     // pre-scaled by log2(e)
__device__ uint16_t g_H[(size_t)B_ * C_ * N_];

// ---------------- helpers ----------------
__device__ __forceinline__ uint32_t f16x2(float lo, float hi) {
    uint32_t r;
    asm("cvt.rn.f16x2.f32 %0, %1, %2;" : "=r"(r) : "f"(hi), "f"(lo));
    return r;
}
__device__ __forceinline__ float f16lo(uint32_t p) {
    return __half2float(__ushort_as_half((unsigned short)(p & 0xffffu)));
}
__device__ __forceinline__ float f16hi(uint32_t p) {
    return __half2float(__ushort_as_half((unsigned short)(p >> 16)));
}
__device__ __forceinline__ float ex2(float x) {
    float r; asm("ex2.approx.f32 %0, %1;" : "=f"(r) : "f"(x)); return r;
}
__device__ __forceinline__ void mma_f16(float* c,
    uint32_t a0, uint32_t a1, uint32_t a2, uint32_t a3,
    uint32_t b0, uint32_t b1) {
    asm volatile("mma.sync.aligned.m16n8k16.row.col.f32.f16.f16.f32 "
        "{%0,%1,%2,%3},{%4,%5,%6,%7},{%8,%9},{%0,%1,%2,%3};"
        : "+f"(c[0]), "+f"(c[1]), "+f"(c[2]), "+f"(c[3])
        : "r"(a0), "r"(a1), "r"(a2), "r"(a3), "r"(b0), "r"(b1));
}
__device__ __forceinline__ void cp16(uint32_t dst, const void* src) {
    asm volatile("cp.async.cg.shared.global [%0], [%1], 16;" :: "r"(dst), "l"(src));
}
__device__ __forceinline__ void cp_commit() { asm volatile("cp.async.commit_group;"); }
__device__ __forceinline__ void cp_wait0()  { asm volatile("cp.async.wait_group 0;"); }
__device__ __forceinline__ unsigned long long ffma2(unsigned long long a,
                                                    unsigned long long b,
                                                    unsigned long long c) {
    unsigned long long d;
    asm("fma.rn.f32x2 %0, %1, %2, %3;" : "=l"(d) : "l"(a), "l"(b), "l"(c));
    return d;
}
__device__ __forceinline__ unsigned long long pack2(float x) {
    unsigned long long r;
    unsigned int xi = __float_as_uint(x);
    asm("mov.b64 %0, {%1, %1};" : "=l"(r) : "r"(xi));
    return r;
}
__device__ __forceinline__ unsigned long long pack2v(float a, float b) {
    unsigned long long r;
    asm("mov.b64 %0, {%1, %2};" : "=l"(r)
        : "r"(__float_as_uint(a)), "r"(__float_as_uint(b)));
    return r;
}
__device__ __forceinline__ float2 unpack2(unsigned long long v) {
    unsigned int lo, hi;
    asm("mov.b64 {%0, %1}, %2;" : "=r"(lo), "=r"(hi) : "l"(v));
    return make_float2(__uint_as_float(lo), __uint_as_float(hi));
}

// ---------------------------------------------------------------------------
// Projection (unchanged from round 6): thread computes 8 rows x 4 n.
// rg 0-1 -> F (fp16 hi/lo), 2-3 -> G (scaled by log2e, hi/lo),
// 4-11 -> H (fp16, transposed [d][n]). Block: 128 n x 32 rows.
// ---------------------------------------------------------------------------
__global__ __launch_bounds__(128) void proj_kernel(
    const float* __restrict__ feat,
    const float* __restrict__ WF,
    const float* __restrict__ WG,
    const float* __restrict__ WH)
{
    __shared__ float sW[256 * 36];
    const int rg = blockIdx.y;
    const int b  = blockIdx.z;

    const float* W;
    int r0, mode;                      // 0=F, 1=G, 2=H
    if (rg < 2)      { W = WF; r0 = rg * 32;       mode = 0; }
    else if (rg < 4) { W = WG; r0 = (rg - 2) * 32; mode = 1; }
    else             { W = WH; r0 = (rg - 4) * 32; mode = 2; }

    for (int i = threadIdx.x; i < 32 * 256; i += 128) {
        int r = i >> 8, c = i & 255;
        sW[c * 36 + r] = W[(size_t)(r0 + r) * C_ + c];
    }
    __syncthreads();

    const int q  = threadIdx.x & 31;
    const int rh = threadIdx.x >> 5;
    const int n  = blockIdx.x * 128 + q * 4;
    const float* fb = feat + (size_t)b * C_ * N_;
    const float* wp = sW + rh * 8;

    unsigned long long acc[8][2];
#pragma unroll
    for (int j = 0; j < 8; j++) { acc[j][0] = 0ULL; acc[j][1] = 0ULL; }

#pragma unroll 4
    for (int c = 0; c < C_; c++) {
        float4 x = __ldg((const float4*)(fb + (size_t)c * N_ + n));
        unsigned long long x01 = pack2v(x.x, x.y);
        unsigned long long x23 = pack2v(x.z, x.w);
        float4 w0 = *(const float4*)(wp + c * 36);
        float4 w1 = *(const float4*)(wp + c * 36 + 4);
#pragma unroll
        for (int j = 0; j < 8; j++) {
            float wj = (j < 4) ? ((const float*)&w0)[j] : ((const float*)&w1)[j - 4];
            unsigned long long w2 = pack2(wj);
            acc[j][0] = ffma2(x01, w2, acc[j][0]);
            acc[j][1] = ffma2(x23, w2, acc[j][1]);
        }
    }

    float val[8][4];
#pragma unroll
    for (int j = 0; j < 8; j++) {
        float2 a = unpack2(acc[j][0]);
        float2 c2 = unpack2(acc[j][1]);
        val[j][0] = a.x; val[j][1] = a.y; val[j][2] = c2.x; val[j][3] = c2.y;
    }

    if (mode == 2) {
#pragma unroll
        for (int j = 0; j < 8; j++) {
            const int d = r0 + rh * 8 + j;
            uint2 o;
            o.x = f16x2(val[j][0], val[j][1]);
            o.y = f16x2(val[j][2], val[j][3]);
            *(uint2*)(g_H + ((size_t)b * C_ + d) * N_ + n) = o;
        }
    } else {
        const float scale = (mode == 1) ? LOG2E : 1.0f;
        uint32_t* dstb = (mode == 1 ? g_G : g_F);
#pragma unroll
        for (int e = 0; e < 4; e++) {
            uint32_t u[8];
#pragma unroll
            for (int jp = 0; jp < 4; jp++) {
                float x0 = val[2 * jp][e] * scale;
                float x1 = val[2 * jp + 1][e] * scale;
                uint32_t hi2 = f16x2(x0, x1);
                uint32_t lo2 = f16x2(x0 - f16lo(hi2), x1 - f16hi(hi2));
                u[2 * jp] = hi2; u[2 * jp + 1] = lo2;
            }
            uint32_t* dst = dstb + ((size_t)b * N_ + n + e) * 64 + r0 + rh * 8;
            uint4 U0; U0.x = u[0]; U0.y = u[1]; U0.z = u[2]; U0.w = u[3];
            uint4 U1; U1.x = u[4]; U1.y = u[5]; U1.z = u[6]; U1.w = u[7];
            *(uint4*)dst = U0;
            *(uint4*)(dst + 4) = U1;
        }
    }
}

// ---------------------------------------------------------------------------
// fp16 hi/lo flash attention. NOW: CTA = 64 q-rows, 4 warps, 2 CTAs/SM
// (independent CTAs fill each other's softmax/sync bubbles).
// Warp-level math identical to round 6: warp = 16 rows x 256 d,
// m-tiles of 32, cp.async double-buffered, S 3-pass fp16, PV 1-pass fp16.
// ---------------------------------------------------------------------------
#define GROW 72                          // u32 per G/F smem row (64 + pad)
#define HROW 20                          // u32 per H smem row (16 + pad)
#define SG  0                            // NB * 72 = 4608 u32
#define SF  (NB * GROW)
#define FPL (MT * GROW)                  // 2304
#define SH  (SF + 2 * FPL)
#define HPL (C_ * HROW)                  // 5120
#define SMEMU (SH + 2 * HPL)             // 19456 u32
#define SMEMB (SMEMU * 4)                // 77824 B  (x2 CTAs = 155648 <= 228KB)

__global__ __launch_bounds__(128, 2) void attn_kernel(
    const float* __restrict__ input,
    const float* __restrict__ gamma_p,
    float* __restrict__ out)
{
    extern __shared__ uint32_t sm[];
    uint32_t smu;
    asm("{ .reg .u64 t; cvta.to.shared.u64 t, %1; cvt.u32.u64 %0, t; }"
        : "=r"(smu) : "l"(sm));

    const int tid  = threadIdx.x;
    const int lane = tid & 31;
    const int w    = tid >> 5;       // warp 0..3, owns rows [16w,16w+16)
    const int gr   = lane >> 2;
    const int tg   = lane & 3;
    const int n0   = blockIdx.x * NB;
    const int b    = blockIdx.y;

    const uint32_t* FG = g_F + (size_t)b * N_ * 64;
    const uint32_t* HG = (const uint32_t*)(g_H + (size_t)b * C_ * N_); // [d][n] fp16

    // stage G tile (NB rows x 64 u32) once via cp.async
    {
        const uint32_t* GG = g_G + ((size_t)b * N_ + n0) * 64;
        for (int i = tid; i < NB * 16; i += 128) {
            int r = i >> 4, ch = i & 15;
            cp16(smu + (SG + r * GROW + ch * 4) * 4, GG + r * 64 + ch * 4);
        }
    }
    // prefetch m-tile 0 into buf 0
    {
        for (int i = tid; i < 512; i += 128) {
            int r = i >> 4, ch = i & 15;
            cp16(smu + (SF + r * GROW + ch * 4) * 4, FG + (size_t)r * 64 + ch * 4);
        }
        for (int i = tid; i < 1024; i += 128) {
            int r = i >> 2, ch = i & 3;   // r = d 0..255
            cp16(smu + (SH + r * HROW + ch * 4) * 4, HG + (size_t)r * 2048 + ch * 4);
        }
        cp_commit();
    }

    float oacc[32][4];
#pragma unroll
    for (int i = 0; i < 32; i++) {
        oacc[i][0] = 0.f; oacc[i][1] = 0.f; oacc[i][2] = 0.f; oacc[i][3] = 0.f;
    }
    const float NEG_INF = __int_as_float(0xff800000);
    float mrow0 = NEG_INF, mrow1 = NEG_INF, lsum0 = 0.f, lsum1 = 0.f;

    const uint32_t* g0 = sm + SG + (w * 16 + gr) * GROW;
    const uint32_t* g1 = g0 + 8 * GROW;

#pragma unroll 1
    for (int t = 0; t < N_ / MT; t++) {
        cp_wait0();
        __syncthreads();

        const int cur = t & 1;
        if (t + 1 < N_ / MT) {
            const int m0n = (t + 1) * MT;
            const int nb = cur ^ 1;
            for (int i = tid; i < 512; i += 128) {
                int r = i >> 4, ch = i & 15;
                cp16(smu + (SF + nb * FPL + r * GROW + ch * 4) * 4,
                     FG + (size_t)(m0n + r) * 64 + ch * 4);
            }
            for (int i = tid; i < 1024; i += 128) {
                int r = i >> 2, ch = i & 3;
                cp16(smu + (SH + nb * HPL + r * HROW + ch * 4) * 4,
                     HG + (size_t)r * 2048 + m0n / 2 + ch * 4);
            }
            cp_commit();
        }

        const uint32_t* sFc = sm + SF + cur * FPL;
        const uint32_t* sHc = sm + SH + cur * HPL;

        // ---- S tile: sc[ms] = 16n x 8m C-frags, 3-pass fp16 k16 ----
        float sc[4][4];
#pragma unroll
        for (int ms = 0; ms < 4; ms++) {
            sc[ms][0] = 0.f; sc[ms][1] = 0.f; sc[ms][2] = 0.f; sc[ms][3] = 0.f;
        }
#pragma unroll
        for (int kc = 0; kc < 4; kc++) {
            const int o0 = kc * 16 + 2 * tg;
            uint2 A0 = *(const uint2*)(g0 + o0);       // (hi, lo)
            uint2 A2 = *(const uint2*)(g0 + o0 + 8);
            uint2 A1 = *(const uint2*)(g1 + o0);
            uint2 A3 = *(const uint2*)(g1 + o0 + 8);
#pragma unroll
            for (int ms = 0; ms < 4; ms++) {
                const uint32_t* f = sFc + (ms * 8 + gr) * GROW;
                uint2 B0 = *(const uint2*)(f + o0);
                uint2 B1 = *(const uint2*)(f + o0 + 8);
                mma_f16(sc[ms], A0.x, A1.x, A2.x, A3.x, B0.x, B1.x);
                mma_f16(sc[ms], A0.x, A1.x, A2.x, A3.x, B0.y, B1.y);
                mma_f16(sc[ms], A0.y, A1.y, A2.y, A3.y, B0.x, B1.x);
            }
        }

        // ---- online softmax (log2 domain), lazy O-rescale ----
        float t0 = NEG_INF, t1 = NEG_INF;
#pragma unroll
        for (int ms = 0; ms < 4; ms++) {
            t0 = fmaxf(t0, fmaxf(sc[ms][0], sc[ms][1]));
            t1 = fmaxf(t1, fmaxf(sc[ms][2], sc[ms][3]));
        }
        t0 = fmaxf(t0, __shfl_xor_sync(0xffffffffu, t0, 1));
        t0 = fmaxf(t0, __shfl_xor_sync(0xffffffffu, t0, 2));
        t1 = fmaxf(t1, __shfl_xor_sync(0xffffffffu, t1, 1));
        t1 = fmaxf(t1, __shfl_xor_sync(0xffffffffu, t1, 2));

        const float mn0 = fmaxf(mrow0, t0);
        const float mn1 = fmaxf(mrow1, t1);
        const bool up = (mn0 != mrow0) || (mn1 != mrow1);
        if (__any_sync(0xffffffffu, up)) {
            const float cr0 = ex2(mrow0 - mn0);
            const float cr1 = ex2(mrow1 - mn1);
            lsum0 *= cr0; lsum1 *= cr1;
#pragma unroll
            for (int dt = 0; dt < 32; dt++) {
                oacc[dt][0] *= cr0; oacc[dt][1] *= cr0;
                oacc[dt][2] *= cr1; oacc[dt][3] *= cr1;
            }
            mrow0 = mn0; mrow1 = mn1;
        }
#pragma unroll
        for (int ms = 0; ms < 4; ms++) {
            sc[ms][0] = ex2(sc[ms][0] - mrow0);
            sc[ms][1] = ex2(sc[ms][1] - mrow0);
            sc[ms][2] = ex2(sc[ms][2] - mrow1);
            sc[ms][3] = ex2(sc[ms][3] - mrow1);
            lsum0 += sc[ms][0] + sc[ms][1];
            lsum1 += sc[ms][2] + sc[ms][3];
        }

        // ---- PV: O += P * H, 1-pass fp16 ----
#pragma unroll
        for (int j = 0; j < 2; j++) {
            const float* cA = sc[2 * j];
            const float* cB = sc[2 * j + 1];
            uint32_t p0 = f16x2(cA[0], cA[1]);
            uint32_t p1 = f16x2(cA[2], cA[3]);
            uint32_t p2 = f16x2(cB[0], cB[1]);
            uint32_t p3 = f16x2(cB[2], cB[3]);
            const uint32_t* hb = sHc + gr * HROW + j * 8;
#pragma unroll
            for (int dt = 0; dt < 32; dt++) {
                const uint32_t* hr = hb + dt * 8 * HROW;
                uint32_t b0 = hr[tg];
                uint32_t b1 = hr[tg + 4];
                mma_f16(oacc[dt], p0, p1, p2, p3, b0, b1);
            }
        }
    }

    // ---- epilogue: l reduce, out = gamma*(O/l) + input, flat [B,N,C] ----
    lsum0 += __shfl_xor_sync(0xffffffffu, lsum0, 1);
    lsum0 += __shfl_xor_sync(0xffffffffu, lsum0, 2);
    lsum1 += __shfl_xor_sync(0xffffffffu, lsum1, 1);
    lsum1 += __shfl_xor_sync(0xffffffffu, lsum1, 2);
    const float inv0 = 1.0f / lsum0;
    const float inv1 = 1.0f / lsum1;
    const float gm = __ldg(gamma_p);

    const int r0 = n0 + w * 16 + gr;
    const int r1 = r0 + 8;
    const size_t base0 = ((size_t)b * N_ + r0) * C_ + tg * 2;
    const size_t base1 = ((size_t)b * N_ + r1) * C_ + tg * 2;
#pragma unroll
    for (int dt = 0; dt < 32; dt++) {
        float2 iv0 = *(const float2*)(input + base0 + dt * 8);
        float2 iv1 = *(const float2*)(input + base1 + dt * 8);
        float2 ov0, ov1;
        ov0.x = fmaf(gm, oacc[dt][0] * inv0, iv0.x);
        ov0.y = fmaf(gm, oacc[dt][1] * inv0, iv0.y);
        ov1.x = fmaf(gm, oacc[dt][2] * inv1, iv1.x);
        ov1.y = fmaf(gm, oacc[dt][3] * inv1, iv1.y);
        *(float2*)(out + base0 + dt * 8) = ov0;
        *(float2*)(out + base1 + dt * 8) = ov1;
    }
}

// ---------------------------------------------------------------------------
extern "C" void kernel_launch(void* const* d_in, const int* in_sizes, int n_in,
                              void* d_out, int out_size) {
    (void)in_sizes; (void)n_in; (void)out_size;
    const float* input = (const float*)d_in[0];
    const float* feat  = (const float*)d_in[1];   // nms_feat
    const float* WF    = (const float*)d_in[2];
    const float* WG    = (const float*)d_in[3];
    const float* WH    = (const float*)d_in[4];
    const float* gamma = (const float*)d_in[5];
    float* out = (float*)d_out;

    cudaFuncSetAttribute(attn_kernel,
                         cudaFuncAttributeMaxDynamicSharedMemorySize, SMEMB);

    proj_kernel<<<dim3(N_ / 128, 12, B_), 128>>>(feat, WF, WG, WH);
    attn_kernel<<<dim3(N_ / NB, B_), 128, SMEMB>>>(input, gamma, out);
}

// round 9
// speedup vs baseline: 1.0418x; 1.0418x over previous
#include <cuda_runtime.h>
#include <cuda_fp16.h>
#include <cstdint>

#define B_ 8
#define C_ 256
#define N_ 4096
#define K_ 64
#define MT 32
#define LOG2E 1.4426950408889634f

// Scratch (fp16 hi/lo packed), PERMUTED for wide LDS fragment loads.
// F/G row (per n): 32 k-pairs in 4 blocks of 8; within a block, pair qb is
// stored at position perm(qb) = (qb&3)*2 + (qb>>2); each position = (hi,lo).
// H: fp16 single, transposed [b][d][m-pairs], same per-8-block permutation.
__device__ uint32_t g_F[(size_t)B_ * N_ * 64];
__device__ uint32_t g_G[(size_t)B_ * N_ * 64];     // pre-scaled by log2(e)
__device__ uint16_t g_H[(size_t)B_ * C_ * N_];

// ---------------- helpers ----------------
__device__ __forceinline__ uint32_t f16x2(float lo, float hi) {
    uint32_t r;
    asm("cvt.rn.f16x2.f32 %0, %1, %2;" : "=r"(r) : "f"(hi), "f"(lo));
    return r;
}
__device__ __forceinline__ float f16lo(uint32_t p) {
    return __half2float(__ushort_as_half((unsigned short)(p & 0xffffu)));
}
__device__ __forceinline__ float f16hi(uint32_t p) {
    return __half2float(__ushort_as_half((unsigned short)(p >> 16)));
}
__device__ __forceinline__ float ex2(float x) {
    float r; asm("ex2.approx.f32 %0, %1;" : "=f"(r) : "f"(x)); return r;
}
__device__ __forceinline__ void mma_f16(float* c,
    uint32_t a0, uint32_t a1, uint32_t a2, uint32_t a3,
    uint32_t b0, uint32_t b1) {
    asm volatile("mma.sync.aligned.m16n8k16.row.col.f32.f16.f16.f32 "
        "{%0,%1,%2,%3},{%4,%5,%6,%7},{%8,%9},{%0,%1,%2,%3};"
        : "+f"(c[0]), "+f"(c[1]), "+f"(c[2]), "+f"(c[3])
        : "r"(a0), "r"(a1), "r"(a2), "r"(a3), "r"(b0), "r"(b1));
}
__device__ __forceinline__ void cp16(uint32_t dst, const void* src) {
    asm volatile("cp.async.cg.shared.global [%0], [%1], 16;" :: "r"(dst), "l"(src));
}
__device__ __forceinline__ void cp_commit() { asm volatile("cp.async.commit_group;"); }
__device__ __forceinline__ void cp_wait0()  { asm volatile("cp.async.wait_group 0;"); }
__device__ __forceinline__ unsigned long long ffma2(unsigned long long a,
                                                    unsigned long long b,
                                                    unsigned long long c) {
    unsigned long long d;
    asm("fma.rn.f32x2 %0, %1, %2, %3;" : "=l"(d) : "l"(a), "l"(b), "l"(c));
    return d;
}
__device__ __forceinline__ unsigned long long pack2(float x) {
    unsigned long long r;
    unsigned int xi = __float_as_uint(x);
    asm("mov.b64 %0, {%1, %1};" : "=l"(r) : "r"(xi));
    return r;
}
__device__ __forceinline__ unsigned long long pack2v(float a, float b) {
    unsigned long long r;
    asm("mov.b64 %0, {%1, %2};" : "=l"(r)
        : "r"(__float_as_uint(a)), "r"(__float_as_uint(b)));
    return r;
}
__device__ __forceinline__ float2 unpack2(unsigned long long v) {
    unsigned int lo, hi;
    asm("mov.b64 {%0, %1}, %2;" : "=r"(lo), "=r"(hi) : "l"(v));
    return make_float2(__uint_as_float(lo), __uint_as_float(hi));
}

// ---------------------------------------------------------------------------
// Projection: thread computes 8 rows x 4 n. Same math as round 6 (outputs
// bit-identical); stores go to the PERMUTED layouts described above.
// rg 0-1 -> F (fp16 hi/lo), 2-3 -> G (scaled), 4-11 -> H ([d][n] fp16).
// ---------------------------------------------------------------------------
__global__ __launch_bounds__(128) void proj_kernel(
    const float* __restrict__ feat,
    const float* __restrict__ WF,
    const float* __restrict__ WG,
    const float* __restrict__ WH)
{
    __shared__ float sW[256 * 36];
    const int rg = blockIdx.y;
    const int b  = blockIdx.z;

    const float* W;
    int r0, mode;                      // 0=F, 1=G, 2=H
    if (rg < 2)      { W = WF; r0 = rg * 32;       mode = 0; }
    else if (rg < 4) { W = WG; r0 = (rg - 2) * 32; mode = 1; }
    else             { W = WH; r0 = (rg - 4) * 32; mode = 2; }

    for (int i = threadIdx.x; i < 32 * 256; i += 128) {
        int r = i >> 8, c = i & 255;
        sW[c * 36 + r] = W[(size_t)(r0 + r) * C_ + c];
    }
    __syncthreads();

    const int q  = threadIdx.x & 31;
    const int rh = threadIdx.x >> 5;
    const int n  = blockIdx.x * 128 + q * 4;
    const float* fb = feat + (size_t)b * C_ * N_;
    const float* wp = sW + rh * 8;

    unsigned long long acc[8][2];
#pragma unroll
    for (int j = 0; j < 8; j++) { acc[j][0] = 0ULL; acc[j][1] = 0ULL; }

#pragma unroll 4
    for (int c = 0; c < C_; c++) {
        float4 x = __ldg((const float4*)(fb + (size_t)c * N_ + n));
        unsigned long long x01 = pack2v(x.x, x.y);
        unsigned long long x23 = pack2v(x.z, x.w);
        float4 w0 = *(const float4*)(wp + c * 36);
        float4 w1 = *(const float4*)(wp + c * 36 + 4);
#pragma unroll
        for (int j = 0; j < 8; j++) {
            float wj = (j < 4) ? ((const float*)&w0)[j] : ((const float*)&w1)[j - 4];
            unsigned long long w2 = pack2(wj);
            acc[j][0] = ffma2(x01, w2, acc[j][0]);
            acc[j][1] = ffma2(x23, w2, acc[j][1]);
        }
    }

    float val[8][4];
#pragma unroll
    for (int j = 0; j < 8; j++) {
        float2 a = unpack2(acc[j][0]);
        float2 c2 = unpack2(acc[j][1]);
        val[j][0] = a.x; val[j][1] = a.y; val[j][2] = c2.x; val[j][3] = c2.y;
    }

    if (mode == 2) {
        // H: row d holds 2048 u32 (m-pairs), permuted within 8-pair blocks.
        const int P0 = n >> 1;                  // first m-pair (even)
        const int base = P0 & ~15;              // 16-pair tile base
        const int pt = P0 & 15;
        const int jj = pt >> 3;
        const int qb = pt & 7;                  // even
        const int pos = base + jj * 8 + (qb & 3) * 2 + (qb >> 2);
#pragma unroll
        for (int j = 0; j < 8; j++) {
            const int d = r0 + rh * 8 + j;
            uint32_t* dst = (uint32_t*)g_H + ((size_t)b * C_ + d) * 2048;
            dst[pos]     = f16x2(val[j][0], val[j][1]);   // pair (n, n+1)
            dst[pos + 2] = f16x2(val[j][2], val[j][3]);   // pair (n+2, n+3)
        }
    } else {
        const float scale = (mode == 1) ? LOG2E : 1.0f;
        uint32_t* dstb = (mode == 1 ? g_G : g_F);
        const int p0  = (r0 + rh * 8) >> 1;     // first k-pair index
        const int blk = p0 >> 3;
        const int qb0 = p0 & 7;                 // 0 or 4
#pragma unroll
        for (int e = 0; e < 4; e++) {
            uint32_t* dst = dstb + ((size_t)b * N_ + n + e) * 64 + blk * 16;
#pragma unroll
            for (int jp = 0; jp < 4; jp++) {
                const int qb = qb0 + jp;
                const int pos = ((qb & 3) * 2 + (qb >> 2)) * 2;
                float x0 = val[2 * jp][e] * scale;
                float x1 = val[2 * jp + 1][e] * scale;
                uint32_t hi2 = f16x2(x0, x1);
                uint32_t lo2 = f16x2(x0 - f16lo(hi2), x1 - f16hi(hi2));
                uint2 o; o.x = hi2; o.y = lo2;
                *(uint2*)(dst + pos) = o;
            }
        }
    }
}

// ---------------------------------------------------------------------------
// fp16 hi/lo flash attention (round-6 shape: 256 thr, 128 q-rows, MT=32,
// cp.async double-buffered). NEW: permuted layouts -> A/B frags load as
// LDS.128 in S and LDS.64 in PV (was 2x LDS.32 per MMA).
// ---------------------------------------------------------------------------
#define GROW 80                          // u32 per G/F smem row (64 + 16 pad)
#define HROW 24                          // u32 per H smem row (16 + 8 pad)
#define SG  0
#define SF  (128 * GROW)                 // 10240
#define FPL (MT * GROW)                  // 2560
#define SH  (SF + 2 * FPL)               // 15360
#define HPL (C_ * HROW)                  // 6144
#define SMEMU (SH + 2 * HPL)             // 27648 u32
#define SMEMB (SMEMU * 4)                // 110592 B

__global__ __launch_bounds__(256, 1) void attn_kernel(
    const float* __restrict__ input,
    const float* __restrict__ gamma_p,
    float* __restrict__ out)
{
    extern __shared__ uint32_t sm[];
    uint32_t smu;
    asm("{ .reg .u64 t; cvta.to.shared.u64 t, %1; cvt.u32.u64 %0, t; }"
        : "=r"(smu) : "l"(sm));

    const int tid  = threadIdx.x;
    const int lane = tid & 31;
    const int w    = tid >> 5;
    const int gr   = lane >> 2;
    const int tg   = lane & 3;
    const int n0   = blockIdx.x * 128;
    const int b    = blockIdx.y;

    const uint32_t* FG = g_F + (size_t)b * N_ * 64;
    const uint32_t* HG = (const uint32_t*)(g_H + (size_t)b * C_ * N_);

    // stage G tile (128 rows x 64 u32) once via cp.async
    {
        const uint32_t* GG = g_G + ((size_t)b * N_ + n0) * 64;
        for (int i = tid; i < 128 * 16; i += 256) {
            int r = i >> 4, ch = i & 15;
            cp16(smu + (SG + r * GROW + ch * 4) * 4, GG + r * 64 + ch * 4);
        }
    }
    // prefetch m-tile 0 into buf 0
    {
        for (int i = tid; i < 512; i += 256) {
            int r = i >> 4, ch = i & 15;
            cp16(smu + (SF + r * GROW + ch * 4) * 4, FG + (size_t)r * 64 + ch * 4);
        }
        for (int i = tid; i < 1024; i += 256) {
            int r = i >> 2, ch = i & 3;   // r = d 0..255
            cp16(smu + (SH + r * HROW + ch * 4) * 4, HG + (size_t)r * 2048 + ch * 4);
        }
        cp_commit();
    }

    float oacc[32][4];
#pragma unroll
    for (int i = 0; i < 32; i++) {
        oacc[i][0] = 0.f; oacc[i][1] = 0.f; oacc[i][2] = 0.f; oacc[i][3] = 0.f;
    }
    const float NEG_INF = __int_as_float(0xff800000);
    float mrow0 = NEG_INF, mrow1 = NEG_INF, lsum0 = 0.f, lsum1 = 0.f;

    const uint32_t* g0 = sm + SG + (w * 16 + gr) * GROW;

#pragma unroll 1
    for (int t = 0; t < N_ / MT; t++) {
        cp_wait0();
        __syncthreads();

        const int cur = t & 1;
        if (t + 1 < N_ / MT) {
            const int m0n = (t + 1) * MT;
            const int nb = cur ^ 1;
            for (int i = tid; i < 512; i += 256) {
                int r = i >> 4, ch = i & 15;
                cp16(smu + (SF + nb * FPL + r * GROW + ch * 4) * 4,
                     FG + (size_t)(m0n + r) * 64 + ch * 4);
            }
            for (int i = tid; i < 1024; i += 256) {
                int r = i >> 2, ch = i & 3;
                cp16(smu + (SH + nb * HPL + r * HROW + ch * 4) * 4,
                     HG + (size_t)r * 2048 + m0n / 2 + ch * 4);
            }
            cp_commit();
        }

        const uint32_t* sFc = sm + SF + cur * FPL;
        const uint32_t* sHc = sm + SH + cur * HPL;

        // ---- S tile: 3-pass fp16 k16; frags via LDS.128 (permuted layout) ----
        float sc[4][4];
#pragma unroll
        for (int ms = 0; ms < 4; ms++) {
            sc[ms][0] = 0.f; sc[ms][1] = 0.f; sc[ms][2] = 0.f; sc[ms][3] = 0.f;
        }
#pragma unroll
        for (int kc = 0; kc < 4; kc++) {
            const uint32_t* ga = g0 + kc * 16 + 4 * tg;
            uint4 Aa = *(const uint4*)ga;               // A0h,A0l,A2h,A2l
            uint4 Ab = *(const uint4*)(ga + 8 * GROW);  // A1h,A1l,A3h,A3l
#pragma unroll
            for (int ms = 0; ms < 4; ms++) {
                const uint32_t* f = sFc + (ms * 8 + gr) * GROW + kc * 16 + 4 * tg;
                uint4 Bv = *(const uint4*)f;            // B0h,B0l,B1h,B1l
                mma_f16(sc[ms], Aa.x, Ab.x, Aa.z, Ab.z, Bv.x, Bv.z);
                mma_f16(sc[ms], Aa.x, Ab.x, Aa.z, Ab.z, Bv.y, Bv.w);
                mma_f16(sc[ms], Aa.y, Ab.y, Aa.w, Ab.w, Bv.x, Bv.z);
            }
        }

        // ---- online softmax (log2 domain), lazy O-rescale ----
        float t0 = NEG_INF, t1 = NEG_INF;
#pragma unroll
        for (int ms = 0; ms < 4; ms++) {
            t0 = fmaxf(t0, fmaxf(sc[ms][0], sc[ms][1]));
            t1 = fmaxf(t1, fmaxf(sc[ms][2], sc[ms][3]));
        }
        t0 = fmaxf(t0, __shfl_xor_sync(0xffffffffu, t0, 1));
        t0 = fmaxf(t0, __shfl_xor_sync(0xffffffffu, t0, 2));
        t1 = fmaxf(t1, __shfl_xor_sync(0xffffffffu, t1, 1));
        t1 = fmaxf(t1, __shfl_xor_sync(0xffffffffu, t1, 2));

        const float mn0 = fmaxf(mrow0, t0);
        const float mn1 = fmaxf(mrow1, t1);
        const bool up = (mn0 != mrow0) || (mn1 != mrow1);
        if (__any_sync(0xffffffffu, up)) {
            const float cr0 = ex2(mrow0 - mn0);
            const float cr1 = ex2(mrow1 - mn1);
            lsum0 *= cr0; lsum1 *= cr1;
#pragma unroll
            for (int dt = 0; dt < 32; dt++) {
                oacc[dt][0] *= cr0; oacc[dt][1] *= cr0;
                oacc[dt][2] *= cr1; oacc[dt][3] *= cr1;
            }
            mrow0 = mn0; mrow1 = mn1;
        }
#pragma unroll
        for (int ms = 0; ms < 4; ms++) {
            sc[ms][0] = ex2(sc[ms][0] - mrow0);
            sc[ms][1] = ex2(sc[ms][1] - mrow0);
            sc[ms][2] = ex2(sc[ms][2] - mrow1);
            sc[ms][3] = ex2(sc[ms][3] - mrow1);
            lsum0 += sc[ms][0] + sc[ms][1];
            lsum1 += sc[ms][2] + sc[ms][3];
        }

        // ---- PV: O += P * H, 1-pass fp16; B-frags via LDS.64 (permuted) ----
#pragma unroll
        for (int j = 0; j < 2; j++) {
            const float* cA = sc[2 * j];
            const float* cB = sc[2 * j + 1];
            uint32_t p0 = f16x2(cA[0], cA[1]);
            uint32_t p1 = f16x2(cA[2], cA[3]);
            uint32_t p2 = f16x2(cB[0], cB[1]);
            uint32_t p3 = f16x2(cB[2], cB[3]);
            const uint32_t* hb = sHc + gr * HROW + j * 8 + 2 * tg;
#pragma unroll
            for (int dt = 0; dt < 32; dt++) {
                uint2 bv = *(const uint2*)(hb + dt * 8 * HROW);
                mma_f16(oacc[dt], p0, p1, p2, p3, bv.x, bv.y);
            }
        }
    }

    // ---- epilogue: l reduce, out = gamma*(O/l) + input, flat [B,N,C] ----
    lsum0 += __shfl_xor_sync(0xffffffffu, lsum0, 1);
    lsum0 += __shfl_xor_sync(0xffffffffu, lsum0, 2);
    lsum1 += __shfl_xor_sync(0xffffffffu, lsum1, 1);
    lsum1 += __shfl_xor_sync(0xffffffffu, lsum1, 2);
    const float inv0 = 1.0f / lsum0;
    const float inv1 = 1.0f / lsum1;
    const float gm = __ldg(gamma_p);

    const int r0 = n0 + w * 16 + gr;
    const int r1 = r0 + 8;
    const size_t base0 = ((size_t)b * N_ + r0) * C_ + tg * 2;
    const size_t base1 = ((size_t)b * N_ + r1) * C_ + tg * 2;
#pragma unroll
    for (int dt = 0; dt < 32; dt++) {
        float2 iv0 = *(const float2*)(input + base0 + dt * 8);
        float2 iv1 = *(const float2*)(input + base1 + dt * 8);
        float2 ov0, ov1;
        ov0.x = fmaf(gm, oacc[dt][0] * inv0, iv0.x);
        ov0.y = fmaf(gm, oacc[dt][1] * inv0, iv0.y);
        ov1.x = fmaf(gm, oacc[dt][2] * inv1, iv1.x);
        ov1.y = fmaf(gm, oacc[dt][3] * inv1, iv1.y);
        *(float2*)(out + base0 + dt * 8) = ov0;
        *(float2*)(out + base1 + dt * 8) = ov1;
    }
}

// ---------------------------------------------------------------------------
extern "C" void kernel_launch(void* const* d_in, const int* in_sizes, int n_in,
                              void* d_out, int out_size) {
    (void)in_sizes; (void)n_in; (void)out_size;
    const float* input = (const float*)d_in[0];
    const float* feat  = (const float*)d_in[1];   // nms_feat
    const float* WF    = (const float*)d_in[2];
    const float* WG    = (const float*)d_in[3];
    const float* WH    = (const float*)d_in[4];
    const float* gamma = (const float*)d_in[5];
    float* out = (float*)d_out;

    cudaFuncSetAttribute(attn_kernel,
                         cudaFuncAttributeMaxDynamicSharedMemorySize, SMEMB);

    proj_kernel<<<dim3(N_ / 128, 12, B_), 128>>>(feat, WF, WG, WH);
    attn_kernel<<<dim3(N_ / 128, B_), 256, SMEMB>>>(input, gamma, out);
}

// round 10
// speedup vs baseline: 1.0447x; 1.0028x over previous
#include <cuda_runtime.h>
#include <cuda_fp16.h>
#include <cstdint>

#define B_ 8
#define C_ 256
#define N_ 4096
#define K_ 64
#define MT 32
#define LOG2E 1.4426950408889634f

// Scratch (fp16 hi/lo packed), PERMUTED for wide LDS fragment loads.
// F/G row (per n): 32 k-pairs in 4 blocks of 8; within a block, pair qb is
// stored at position perm(qb) = (qb&3)*2 + (qb>>2); each position = (hi,lo).
// H: fp16 single, transposed [b][d][m-pairs], same per-8-block permutation.
__device__ uint32_t g_F[(size_t)B_ * N_ * 64];
__device__ uint32_t g_G[(size_t)B_ * N_ * 64];     // pre-scaled by log2(e)
__device__ uint16_t g_H[(size_t)B_ * C_ * N_];

// ---------------- helpers ----------------
__device__ __forceinline__ uint32_t f16x2(float lo, float hi) {
    uint32_t r;
    asm("cvt.rn.f16x2.f32 %0, %1, %2;" : "=r"(r) : "f"(hi), "f"(lo));
    return r;
}
__device__ __forceinline__ float f16lo(uint32_t p) {
    return __half2float(__ushort_as_half((unsigned short)(p & 0xffffu)));
}
__device__ __forceinline__ float f16hi(uint32_t p) {
    return __half2float(__ushort_as_half((unsigned short)(p >> 16)));
}
__device__ __forceinline__ float ex2(float x) {
    float r; asm("ex2.approx.f32 %0, %1;" : "=f"(r) : "f"(x)); return r;
}
__device__ __forceinline__ void mma_f16(float* c,
    uint32_t a0, uint32_t a1, uint32_t a2, uint32_t a3,
    uint32_t b0, uint32_t b1) {
    asm volatile("mma.sync.aligned.m16n8k16.row.col.f32.f16.f16.f32 "
        "{%0,%1,%2,%3},{%4,%5,%6,%7},{%8,%9},{%0,%1,%2,%3};"
        : "+f"(c[0]), "+f"(c[1]), "+f"(c[2]), "+f"(c[3])
        : "r"(a0), "r"(a1), "r"(a2), "r"(a3), "r"(b0), "r"(b1));
}
__device__ __forceinline__ void cp16(uint32_t dst, const void* src) {
    asm volatile("cp.async.cg.shared.global [%0], [%1], 16;" :: "r"(dst), "l"(src));
}
__device__ __forceinline__ void cp_commit() { asm volatile("cp.async.commit_group;"); }
__device__ __forceinline__ void cp_wait0()  { asm volatile("cp.async.wait_group 0;"); }
__device__ __forceinline__ unsigned long long ffma2(unsigned long long a,
                                                    unsigned long long b,
                                                    unsigned long long c) {
    unsigned long long d;
    asm("fma.rn.f32x2 %0, %1, %2, %3;" : "=l"(d) : "l"(a), "l"(b), "l"(c));
    return d;
}
__device__ __forceinline__ unsigned long long pack2(float x) {
    unsigned long long r;
    unsigned int xi = __float_as_uint(x);
    asm("mov.b64 %0, {%1, %1};" : "=l"(r) : "r"(xi));
    return r;
}
__device__ __forceinline__ unsigned long long pack2v(float a, float b) {
    unsigned long long r;
    asm("mov.b64 %0, {%1, %2};" : "=l"(r)
        : "r"(__float_as_uint(a)), "r"(__float_as_uint(b)));
    return r;
}
__device__ __forceinline__ float2 unpack2(unsigned long long v) {
    unsigned int lo, hi;
    asm("mov.b64 {%0, %1}, %2;" : "=r"(lo), "=r"(hi) : "l"(v));
    return make_float2(__uint_as_float(lo), __uint_as_float(hi));
}

// ---------------------------------------------------------------------------
// Projection: thread computes 8 rows x 4 n. Same math as round 6 (outputs
// bit-identical); stores go to the PERMUTED layouts described above.
// rg 0-1 -> F (fp16 hi/lo), 2-3 -> G (scaled), 4-11 -> H ([d][n] fp16).
// ---------------------------------------------------------------------------
__global__ __launch_bounds__(128) void proj_kernel(
    const float* __restrict__ feat,
    const float* __restrict__ WF,
    const float* __restrict__ WG,
    const float* __restrict__ WH)
{
    __shared__ float sW[256 * 36];
    const int rg = blockIdx.y;
    const int b  = blockIdx.z;

    const float* W;
    int r0, mode;                      // 0=F, 1=G, 2=H
    if (rg < 2)      { W = WF; r0 = rg * 32;       mode = 0; }
    else if (rg < 4) { W = WG; r0 = (rg - 2) * 32; mode = 1; }
    else             { W = WH; r0 = (rg - 4) * 32; mode = 2; }

    for (int i = threadIdx.x; i < 32 * 256; i += 128) {
        int r = i >> 8, c = i & 255;
        sW[c * 36 + r] = W[(size_t)(r0 + r) * C_ + c];
    }
    __syncthreads();

    const int q  = threadIdx.x & 31;
    const int rh = threadIdx.x >> 5;
    const int n  = blockIdx.x * 128 + q * 4;
    const float* fb = feat + (size_t)b * C_ * N_;
    const float* wp = sW + rh * 8;

    unsigned long long acc[8][2];
#pragma unroll
    for (int j = 0; j < 8; j++) { acc[j][0] = 0ULL; acc[j][1] = 0ULL; }

#pragma unroll 4
    for (int c = 0; c < C_; c++) {
        float4 x = __ldg((const float4*)(fb + (size_t)c * N_ + n));
        unsigned long long x01 = pack2v(x.x, x.y);
        unsigned long long x23 = pack2v(x.z, x.w);
        float4 w0 = *(const float4*)(wp + c * 36);
        float4 w1 = *(const float4*)(wp + c * 36 + 4);
#pragma unroll
        for (int j = 0; j < 8; j++) {
            float wj = (j < 4) ? ((const float*)&w0)[j] : ((const float*)&w1)[j - 4];
            unsigned long long w2 = pack2(wj);
            acc[j][0] = ffma2(x01, w2, acc[j][0]);
            acc[j][1] = ffma2(x23, w2, acc[j][1]);
        }
    }

    float val[8][4];
#pragma unroll
    for (int j = 0; j < 8; j++) {
        float2 a = unpack2(acc[j][0]);
        float2 c2 = unpack2(acc[j][1]);
        val[j][0] = a.x; val[j][1] = a.y; val[j][2] = c2.x; val[j][3] = c2.y;
    }

    if (mode == 2) {
        // H: row d holds 2048 u32 (m-pairs), permuted within 8-pair blocks.
        const int P0 = n >> 1;                  // first m-pair (even)
        const int base = P0 & ~15;              // 16-pair tile base
        const int pt = P0 & 15;
        const int jj = pt >> 3;
        const int qb = pt & 7;                  // even
        const int pos = base + jj * 8 + (qb & 3) * 2 + (qb >> 2);
#pragma unroll
        for (int j = 0; j < 8; j++) {
            const int d = r0 + rh * 8 + j;
            uint32_t* dst = (uint32_t*)g_H + ((size_t)b * C_ + d) * 2048;
            dst[pos]     = f16x2(val[j][0], val[j][1]);   // pair (n, n+1)
            dst[pos + 2] = f16x2(val[j][2], val[j][3]);   // pair (n+2, n+3)
        }
    } else {
        const float scale = (mode == 1) ? LOG2E : 1.0f;
        uint32_t* dstb = (mode == 1 ? g_G : g_F);
        const int p0  = (r0 + rh * 8) >> 1;     // first k-pair index
        const int blk = p0 >> 3;
        const int qb0 = p0 & 7;                 // 0 or 4
#pragma unroll
        for (int e = 0; e < 4; e++) {
            uint32_t* dst = dstb + ((size_t)b * N_ + n + e) * 64 + blk * 16;
#pragma unroll
            for (int jp = 0; jp < 4; jp++) {
                const int qb = qb0 + jp;
                const int pos = ((qb & 3) * 2 + (qb >> 2)) * 2;
                float x0 = val[2 * jp][e] * scale;
                float x1 = val[2 * jp + 1][e] * scale;
                uint32_t hi2 = f16x2(x0, x1);
                uint32_t lo2 = f16x2(x0 - f16lo(hi2), x1 - f16hi(hi2));
                uint2 o; o.x = hi2; o.y = lo2;
                *(uint2*)(dst + pos) = o;
            }
        }
    }
}

// ---------------------------------------------------------------------------
// fp16 hi/lo flash attention (round-6 shape: 256 thr, 128 q-rows, MT=32,
// cp.async double-buffered). NEW: permuted layouts -> A/B frags load as
// LDS.128 in S and LDS.64 in PV (was 2x LDS.32 per MMA).
// ---------------------------------------------------------------------------
#define GROW 80                          // u32 per G/F smem row (64 + 16 pad)
#define HROW 24                          // u32 per H smem row (16 + 8 pad)
#define SG  0
#define SF  (128 * GROW)                 // 10240
#define FPL (MT * GROW)                  // 2560
#define SH  (SF + 2 * FPL)               // 15360
#define HPL (C_ * HROW)                  // 6144
#define SMEMU (SH + 2 * HPL)             // 27648 u32
#define SMEMB (SMEMU * 4)                // 110592 B

__global__ __launch_bounds__(256, 1) void attn_kernel(
    const float* __restrict__ input,
    const float* __restrict__ gamma_p,
    float* __restrict__ out)
{
    extern __shared__ uint32_t sm[];
    uint32_t smu;
    asm("{ .reg .u64 t; cvta.to.shared.u64 t, %1; cvt.u32.u64 %0, t; }"
        : "=r"(smu) : "l"(sm));

    const int tid  = threadIdx.x;
    const int lane = tid & 31;
    const int w    = tid >> 5;
    const int gr   = lane >> 2;
    const int tg   = lane & 3;
    const int n0   = blockIdx.x * 128;
    const int b    = blockIdx.y;

    const uint32_t* FG = g_F + (size_t)b * N_ * 64;
    const uint32_t* HG = (const uint32_t*)(g_H + (size_t)b * C_ * N_);

    // stage G tile (128 rows x 64 u32) once via cp.async
    {
        const uint32_t* GG = g_G + ((size_t)b * N_ + n0) * 64;
        for (int i = tid; i < 128 * 16; i += 256) {
            int r = i >> 4, ch = i & 15;
            cp16(smu + (SG + r * GROW + ch * 4) * 4, GG + r * 64 + ch * 4);
        }
    }
    // prefetch m-tile 0 into buf 0
    {
        for (int i = tid; i < 512; i += 256) {
            int r = i >> 4, ch = i & 15;
            cp16(smu + (SF + r * GROW + ch * 4) * 4, FG + (size_t)r * 64 + ch * 4);
        }
        for (int i = tid; i < 1024; i += 256) {
            int r = i >> 2, ch = i & 3;   // r = d 0..255
            cp16(smu + (SH + r * HROW + ch * 4) * 4, HG + (size_t)r * 2048 + ch * 4);
        }
        cp_commit();
    }

    float oacc[32][4];
#pragma unroll
    for (int i = 0; i < 32; i++) {
        oacc[i][0] = 0.f; oacc[i][1] = 0.f; oacc[i][2] = 0.f; oacc[i][3] = 0.f;
    }
    const float NEG_INF = __int_as_float(0xff800000);
    float mrow0 = NEG_INF, mrow1 = NEG_INF, lsum0 = 0.f, lsum1 = 0.f;

    const uint32_t* g0 = sm + SG + (w * 16 + gr) * GROW;

#pragma unroll 1
    for (int t = 0; t < N_ / MT; t++) {
        cp_wait0();
        __syncthreads();

        const int cur = t & 1;
        if (t + 1 < N_ / MT) {
            const int m0n = (t + 1) * MT;
            const int nb = cur ^ 1;
            for (int i = tid; i < 512; i += 256) {
                int r = i >> 4, ch = i & 15;
                cp16(smu + (SF + nb * FPL + r * GROW + ch * 4) * 4,
                     FG + (size_t)(m0n + r) * 64 + ch * 4);
            }
            for (int i = tid; i < 1024; i += 256) {
                int r = i >> 2, ch = i & 3;
                cp16(smu + (SH + nb * HPL + r * HROW + ch * 4) * 4,
                     HG + (size_t)r * 2048 + m0n / 2 + ch * 4);
            }
            cp_commit();
        }

        const uint32_t* sFc = sm + SF + cur * FPL;
        const uint32_t* sHc = sm + SH + cur * HPL;

        // ---- S tile: 3-pass fp16 k16; frags via LDS.128 (permuted layout) ----
        float sc[4][4];
#pragma unroll
        for (int ms = 0; ms < 4; ms++) {
            sc[ms][0] = 0.f; sc[ms][1] = 0.f; sc[ms][2] = 0.f; sc[ms][3] = 0.f;
        }
#pragma unroll
        for (int kc = 0; kc < 4; kc++) {
            const uint32_t* ga = g0 + kc * 16 + 4 * tg;
            uint4 Aa = *(const uint4*)ga;               // A0h,A0l,A2h,A2l
            uint4 Ab = *(const uint4*)(ga + 8 * GROW);  // A1h,A1l,A3h,A3l
#pragma unroll
            for (int ms = 0; ms < 4; ms++) {
                const uint32_t* f = sFc + (ms * 8 + gr) * GROW + kc * 16 + 4 * tg;
                uint4 Bv = *(const uint4*)f;            // B0h,B0l,B1h,B1l
                mma_f16(sc[ms], Aa.x, Ab.x, Aa.z, Ab.z, Bv.x, Bv.z);
                mma_f16(sc[ms], Aa.x, Ab.x, Aa.z, Ab.z, Bv.y, Bv.w);
                mma_f16(sc[ms], Aa.y, Ab.y, Aa.w, Ab.w, Bv.x, Bv.z);
            }
        }

        // ---- online softmax (log2 domain), lazy O-rescale ----
        float t0 = NEG_INF, t1 = NEG_INF;
#pragma unroll
        for (int ms = 0; ms < 4; ms++) {
            t0 = fmaxf(t0, fmaxf(sc[ms][0], sc[ms][1]));
            t1 = fmaxf(t1, fmaxf(sc[ms][2], sc[ms][3]));
        }
        t0 = fmaxf(t0, __shfl_xor_sync(0xffffffffu, t0, 1));
        t0 = fmaxf(t0, __shfl_xor_sync(0xffffffffu, t0, 2));
        t1 = fmaxf(t1, __shfl_xor_sync(0xffffffffu, t1, 1));
        t1 = fmaxf(t1, __shfl_xor_sync(0xffffffffu, t1, 2));

        const float mn0 = fmaxf(mrow0, t0);
        const float mn1 = fmaxf(mrow1, t1);
        const bool up = (mn0 != mrow0) || (mn1 != mrow1);
        if (__any_sync(0xffffffffu, up)) {
            const float cr0 = ex2(mrow0 - mn0);
            const float cr1 = ex2(mrow1 - mn1);
            lsum0 *= cr0; lsum1 *= cr1;
#pragma unroll
            for (int dt = 0; dt < 32; dt++) {
                oacc[dt][0] *= cr0; oacc[dt][1] *= cr0;
                oacc[dt][2] *= cr1; oacc[dt][3] *= cr1;
            }
            mrow0 = mn0; mrow1 = mn1;
        }
#pragma unroll
        for (int ms = 0; ms < 4; ms++) {
            sc[ms][0] = ex2(sc[ms][0] - mrow0);
            sc[ms][1] = ex2(sc[ms][1] - mrow0);
            sc[ms][2] = ex2(sc[ms][2] - mrow1);
            sc[ms][3] = ex2(sc[ms][3] - mrow1);
            lsum0 += sc[ms][0] + sc[ms][1];
            lsum1 += sc[ms][2] + sc[ms][3];
        }

        // ---- PV: O += P * H, 1-pass fp16; B-frags via LDS.64 (permuted) ----
#pragma unroll
        for (int j = 0; j < 2; j++) {
            const float* cA = sc[2 * j];
            const float* cB = sc[2 * j + 1];
            uint32_t p0 = f16x2(cA[0], cA[1]);
            uint32_t p1 = f16x2(cA[2], cA[3]);
            uint32_t p2 = f16x2(cB[0], cB[1]);
            uint32_t p3 = f16x2(cB[2], cB[3]);
            const uint32_t* hb = sHc + gr * HROW + j * 8 + 2 * tg;
#pragma unroll
            for (int dt = 0; dt < 32; dt++) {
                uint2 bv = *(const uint2*)(hb + dt * 8 * HROW);
                mma_f16(oacc[dt], p0, p1, p2, p3, bv.x, bv.y);
            }
        }
    }

    // ---- epilogue: l reduce, out = gamma*(O/l) + input, flat [B,N,C] ----
    lsum0 += __shfl_xor_sync(0xffffffffu, lsum0, 1);
    lsum0 += __shfl_xor_sync(0xffffffffu, lsum0, 2);
    lsum1 += __shfl_xor_sync(0xffffffffu, lsum1, 1);
    lsum1 += __shfl_xor_sync(0xffffffffu, lsum1, 2);
    const float inv0 = 1.0f / lsum0;
    const float inv1 = 1.0f / lsum1;
    const float gm = __ldg(gamma_p);

    const int r0 = n0 + w * 16 + gr;
    const int r1 = r0 + 8;
    const size_t base0 = ((size_t)b * N_ + r0) * C_ + tg * 2;
    const size_t base1 = ((size_t)b * N_ + r1) * C_ + tg * 2;
#pragma unroll
    for (int dt = 0; dt < 32; dt++) {
        float2 iv0 = *(const float2*)(input + base0 + dt * 8);
        float2 iv1 = *(const float2*)(input + base1 + dt * 8);
        float2 ov0, ov1;
        ov0.x = fmaf(gm, oacc[dt][0] * inv0, iv0.x);
        ov0.y = fmaf(gm, oacc[dt][1] * inv0, iv0.y);
        ov1.x = fmaf(gm, oacc[dt][2] * inv1, iv1.x);
        ov1.y = fmaf(gm, oacc[dt][3] * inv1, iv1.y);
        *(float2*)(out + base0 + dt * 8) = ov0;
        *(float2*)(out + base1 + dt * 8) = ov1;
    }
}

// ---------------------------------------------------------------------------
extern "C" void kernel_launch(void* const* d_in, const int* in_sizes, int n_in,
                              void* d_out, int out_size) {
    (void)in_sizes; (void)n_in; (void)out_size;
    const float* input = (const float*)d_in[0];
    const float* feat  = (const float*)d_in[1];   // nms_feat
    const float* WF    = (const float*)d_in[2];
    const float* WG    = (const float*)d_in[3];
    const float* WH    = (const float*)d_in[4];
    const float* gamma = (const float*)d_in[5];
    float* out = (float*)d_out;

    cudaFuncSetAttribute(attn_kernel,
                         cudaFuncAttributeMaxDynamicSharedMemorySize, SMEMB);

    proj_kernel<<<dim3(N_ / 128, 12, B_), 128>>>(feat, WF, WG, WH);
    attn_kernel<<<dim3(N_ / 128, B_), 256, SMEMB>>>(input, gamma, out);
}